// round 1
// baseline (speedup 1.0000x reference)
#include <cuda_runtime.h>
#include <math.h>

#define BATCH 4
#define SEQ   2048
#define EMB   1024
#define HEADS 16
#define HDIM  64
#define MROWS (BATCH*SEQ)   /* 8192 */

// Scratch (device globals: allocation-free per harness rules)
__device__ float g_qkv[(size_t)MROWS * 3 * EMB];   // [8192, 3072]
__device__ float g_att[(size_t)MROWS * EMB];       // [8192, 1024]

// ---------------------------------------------------------------------------
// SGEMM: C[M,N] = A[M,K] @ B[K,N] + bias[N]
// 128x128 block tile, BK=8, 8x8 per thread, 256 threads.
// M,N multiples of 128; K multiple of 8 (true for all our shapes).
// ---------------------------------------------------------------------------
__global__ __launch_bounds__(256, 2)
void sgemm_bias_kernel(const float* __restrict__ A, const float* __restrict__ B,
                       const float* __restrict__ bias, float* __restrict__ C,
                       int M, int N, int K)
{
    __shared__ __align__(16) float As[8][128];
    __shared__ __align__(16) float Bs[8][128];

    const int tid = threadIdx.x;
    const int tx  = tid & 15;
    const int ty  = tid >> 4;
    const int bx  = blockIdx.x * 128;
    const int by  = blockIdx.y * 128;

    const int aRow = tid >> 1;          // 0..127
    const int aCol = (tid & 1) << 2;    // 0 or 4
    const int bRow = tid >> 5;          // 0..7
    const int bCol = (tid & 31) << 2;   // 0..124

    const float* Aptr = A + (size_t)(by + aRow) * K + aCol;
    const float* Bptr = B + (size_t)bRow * N + bx + bCol;

    float acc[8][8];
    #pragma unroll
    for (int i = 0; i < 8; i++)
        #pragma unroll
        for (int j = 0; j < 8; j++) acc[i][j] = 0.f;

    for (int k0 = 0; k0 < K; k0 += 8) {
        float4 av = *(const float4*)(Aptr);
        Aptr += 8;
        As[aCol + 0][aRow] = av.x;
        As[aCol + 1][aRow] = av.y;
        As[aCol + 2][aRow] = av.z;
        As[aCol + 3][aRow] = av.w;
        float4 bv = *(const float4*)(Bptr);
        Bptr += (size_t)8 * N;
        *(float4*)(&Bs[bRow][bCol]) = bv;
        __syncthreads();

        #pragma unroll
        for (int k = 0; k < 8; k++) {
            float ra[8], rb[8];
            #pragma unroll
            for (int i = 0; i < 8; i++) ra[i] = As[k][ty * 8 + i];
            #pragma unroll
            for (int j = 0; j < 8; j++) rb[j] = Bs[k][tx * 8 + j];
            #pragma unroll
            for (int i = 0; i < 8; i++)
                #pragma unroll
                for (int j = 0; j < 8; j++)
                    acc[i][j] += ra[i] * rb[j];
        }
        __syncthreads();
    }

    #pragma unroll
    for (int i = 0; i < 8; i++) {
        const size_t row = (size_t)by + ty * 8 + i;
        #pragma unroll
        for (int j = 0; j < 8; j += 4) {
            const int col = bx + tx * 8 + j;
            float4 o;
            o.x = acc[i][j + 0] + bias[col + 0];
            o.y = acc[i][j + 1] + bias[col + 1];
            o.z = acc[i][j + 2] + bias[col + 2];
            o.w = acc[i][j + 3] + bias[col + 3];
            *(float4*)(&C[row * N + col]) = o;
        }
    }
}

// ---------------------------------------------------------------------------
// Flash attention, fp32, causal + ALiBi.
// One CTA per (b, h, 64-row q tile). 256 threads as 16x16, 4x4 microtiles.
// K stored d-major (transposed) in smem for conflict-free float4 reads;
// same buffer is reused for the P tile (row-major) after a sync.
// ---------------------------------------------------------------------------
__global__ __launch_bounds__(256, 2)
void attn_kernel(const float* __restrict__ qkv, float* __restrict__ out)
{
    __shared__ __align__(16) float Qs[64 * 64];   // [row][d]
    __shared__ __align__(16) float KPs[64 * 64];  // K^T: [d][col]; later P: [row][col]
    __shared__ __align__(16) float Vs[64 * 64];   // [k][d]

    const int qt  = blockIdx.x;   // 0..31
    const int h   = blockIdx.y;   // 0..15
    const int b   = blockIdx.z;   // 0..3
    const int tid = threadIdx.x;
    const int tx  = tid & 15;
    const int ty  = tid >> 4;
    const int q0  = qt * 64;

    // slope[h] = (2^8)^(-(h+1)/H) = 2^(-0.5*(h+1)) for H=16
    const float slope = exp2f(-0.5f * (float)(h + 1));

    // loader mapping: row lr (0..63), 16 contiguous d at lc
    const int lr = tid >> 2;
    const int lc = (tid & 3) << 4;

    const size_t rs = 3 * EMB;  // qkv row stride
    const float* base = qkv + (size_t)b * SEQ * rs + h * HDIM;

    // Load Q tile, pre-scaled by 1/sqrt(D)
    {
        const float* g = base + (size_t)(q0 + lr) * rs + lc;
        #pragma unroll
        for (int j = 0; j < 16; j += 4) {
            float4 v = *(const float4*)(g + j);
            v.x *= 0.125f; v.y *= 0.125f; v.z *= 0.125f; v.w *= 0.125f;
            *(float4*)(&Qs[lr * 64 + lc + j]) = v;
        }
    }

    float m[4], l[4], o[4][4];
    #pragma unroll
    for (int i = 0; i < 4; i++) {
        m[i] = -1e30f; l[i] = 0.f;
        #pragma unroll
        for (int j = 0; j < 4; j++) o[i][j] = 0.f;
    }

    for (int kt = 0; kt <= qt; kt++) {
        __syncthreads();  // prior-tile PV reads of KPs/Vs done (also covers Q load, iter 0)
        const int k0 = kt * 64;
        {
            const float* kg = base + EMB     + (size_t)(k0 + lr) * rs + lc;
            const float* vg = base + 2 * EMB + (size_t)(k0 + lr) * rs + lc;
            #pragma unroll
            for (int j = 0; j < 16; j += 4) {
                float4 kv = *(const float4*)(kg + j);
                KPs[(lc + j + 0) * 64 + lr] = kv.x;   // transpose K
                KPs[(lc + j + 1) * 64 + lr] = kv.y;
                KPs[(lc + j + 2) * 64 + lr] = kv.z;
                KPs[(lc + j + 3) * 64 + lr] = kv.w;
                float4 vv = *(const float4*)(vg + j);
                *(float4*)(&Vs[lr * 64 + lc + j]) = vv;
            }
        }
        __syncthreads();

        // S = Q K^T  (4x4 per thread)
        float s[4][4];
        #pragma unroll
        for (int i = 0; i < 4; i++)
            #pragma unroll
            for (int j = 0; j < 4; j++) s[i][j] = 0.f;

        #pragma unroll 8
        for (int d = 0; d < 64; d++) {
            float ra[4];
            #pragma unroll
            for (int i = 0; i < 4; i++) ra[i] = Qs[(ty * 4 + i) * 64 + d];
            float4 rb = *(const float4*)(&KPs[d * 64 + tx * 4]);
            #pragma unroll
            for (int i = 0; i < 4; i++) {
                s[i][0] += ra[i] * rb.x;
                s[i][1] += ra[i] * rb.y;
                s[i][2] += ra[i] * rb.z;
                s[i][3] += ra[i] * rb.w;
            }
        }

        // ALiBi + causal mask
        #pragma unroll
        for (int i = 0; i < 4; i++) {
            const int qrow = q0 + ty * 4 + i;
            #pragma unroll
            for (int j = 0; j < 4; j++) {
                const int kcol = k0 + tx * 4 + j;
                s[i][j] += slope * (float)(kcol - qrow);
                if (kcol > qrow) s[i][j] = -1e30f;
            }
        }

        // online softmax update
        #pragma unroll
        for (int i = 0; i < 4; i++) {
            float tm = fmaxf(fmaxf(s[i][0], s[i][1]), fmaxf(s[i][2], s[i][3]));
            tm = fmaxf(tm, __shfl_xor_sync(0xffffffffu, tm, 1));
            tm = fmaxf(tm, __shfl_xor_sync(0xffffffffu, tm, 2));
            tm = fmaxf(tm, __shfl_xor_sync(0xffffffffu, tm, 4));
            tm = fmaxf(tm, __shfl_xor_sync(0xffffffffu, tm, 8));
            const float mn   = fmaxf(m[i], tm);
            const float corr = __expf(m[i] - mn);
            float ts = 0.f;
            #pragma unroll
            for (int j = 0; j < 4; j++) {
                s[i][j] = __expf(s[i][j] - mn);
                ts += s[i][j];
            }
            ts += __shfl_xor_sync(0xffffffffu, ts, 1);
            ts += __shfl_xor_sync(0xffffffffu, ts, 2);
            ts += __shfl_xor_sync(0xffffffffu, ts, 4);
            ts += __shfl_xor_sync(0xffffffffu, ts, 8);
            l[i] = l[i] * corr + ts;
            m[i] = mn;
            #pragma unroll
            for (int j = 0; j < 4; j++) o[i][j] *= corr;
        }

        __syncthreads();  // everyone done reading K^T from KPs
        #pragma unroll
        for (int i = 0; i < 4; i++) {
            float4 pv = make_float4(s[i][0], s[i][1], s[i][2], s[i][3]);
            *(float4*)(&KPs[(ty * 4 + i) * 64 + tx * 4]) = pv;   // P row-major
        }
        __syncthreads();

        // O += P @ V
        #pragma unroll 8
        for (int d = 0; d < 64; d++) {
            float pa[4];
            #pragma unroll
            for (int i = 0; i < 4; i++) pa[i] = KPs[(ty * 4 + i) * 64 + d];
            float4 vb = *(const float4*)(&Vs[d * 64 + tx * 4]);
            #pragma unroll
            for (int i = 0; i < 4; i++) {
                o[i][0] += pa[i] * vb.x;
                o[i][1] += pa[i] * vb.y;
                o[i][2] += pa[i] * vb.z;
                o[i][3] += pa[i] * vb.w;
            }
        }
    }

    // epilogue: normalize and store [b, q, h*64 + d]
    float* og = out + ((size_t)b * SEQ + q0) * EMB + h * HDIM;
    #pragma unroll
    for (int i = 0; i < 4; i++) {
        const float inv = 1.f / l[i];
        float4 r = make_float4(o[i][0] * inv, o[i][1] * inv,
                               o[i][2] * inv, o[i][3] * inv);
        *(float4*)(&og[(size_t)(ty * 4 + i) * EMB + tx * 4]) = r;
    }
}

// ---------------------------------------------------------------------------
extern "C" void kernel_launch(void* const* d_in, const int* in_sizes, int n_in,
                              void* d_out, int out_size)
{
    const float* x    = (const float*)d_in[0];
    // d_in[1] = mask (bool tril) — causality is computed analytically, unused
    const float* Wqkv = (const float*)d_in[2];
    const float* bqkv = (const float*)d_in[3];
    const float* Wout = (const float*)d_in[4];
    const float* bout = (const float*)d_in[5];
    float* out = (float*)d_out;

    float *qkv_ptr = nullptr, *att_ptr = nullptr;
    cudaGetSymbolAddress((void**)&qkv_ptr, g_qkv);
    cudaGetSymbolAddress((void**)&att_ptr, g_att);

    // 1) qkv = x @ W_qkv + b_qkv      [8192,1024]x[1024,3072]
    sgemm_bias_kernel<<<dim3(3 * EMB / 128, MROWS / 128), 256>>>(
        x, Wqkv, bqkv, qkv_ptr, MROWS, 3 * EMB, EMB);

    // 2) attention (causal + ALiBi + softmax), writes [8192,1024]
    attn_kernel<<<dim3(SEQ / 64, HEADS, BATCH), 256>>>(qkv_ptr, att_ptr);

    // 3) out = att @ W_out + b_out    [8192,1024]x[1024,1024]
    sgemm_bias_kernel<<<dim3(EMB / 128, MROWS / 128), 256>>>(
        att_ptr, Wout, bout, out, MROWS, EMB, EMB);
}

// round 3
// speedup vs baseline: 1.6121x; 1.6121x over previous
#include <cuda_runtime.h>
#include <cstdint>
#include <math.h>

#define BATCH 4
#define SEQ   2048
#define EMB   1024
#define HEADS 16
#define HDIM  64
#define MROWS (BATCH*SEQ)   /* 8192 */

// Scratch (device globals: allocation-free per harness rules)
__device__ float g_qkv[(size_t)MROWS * 3 * EMB];   // [8192, 3072]
__device__ float g_att[(size_t)MROWS * EMB];       // [8192, 1024]
__device__ float g_xc [(size_t)MROWS * EMB];       // x, rna(tf32)-rounded
__device__ float g_wqt[(size_t)3 * EMB * EMB];     // W_qkv^T [3072,1024], rna
__device__ float g_wot[(size_t)EMB * EMB];         // W_out^T [1024,1024], rna

// ---------------------------------------------------------------------------
// helpers (portable PTX only: cp.async + mma.sync compile at compute_103)
// ---------------------------------------------------------------------------
__device__ __forceinline__ uint32_t smem_u32(const void* p) {
    uint32_t a;
    asm("{ .reg .u64 t; cvta.to.shared.u64 t, %1; cvt.u32.u64 %0, t; }" : "=r"(a) : "l"(p));
    return a;
}
__device__ __forceinline__ float rna_tf32(float v) {
    uint32_t u;
    asm("cvt.rna.tf32.f32 %0, %1;" : "=r"(u) : "f"(v));
    return __uint_as_float(u);
}
__device__ __forceinline__ void cp_async16(uint32_t dst, const void* src) {
    asm volatile("cp.async.cg.shared.global [%0], [%1], 16;" :: "r"(dst), "l"(src));
}
__device__ __forceinline__ void cp_commit() {
    asm volatile("cp.async.commit_group;" ::: "memory");
}
template <int N>
__device__ __forceinline__ void cp_wait() {
    asm volatile("cp.async.wait_group %0;" :: "n"(N) : "memory");
}
__device__ __forceinline__ void mma_tf32(float& c0, float& c1, float& c2, float& c3,
                                         uint32_t a0, uint32_t a1, uint32_t a2, uint32_t a3,
                                         uint32_t b0, uint32_t b1) {
    asm volatile(
        "mma.sync.aligned.m16n8k8.row.col.f32.tf32.tf32.f32 "
        "{%0,%1,%2,%3}, {%4,%5,%6,%7}, {%8,%9}, {%0,%1,%2,%3};"
        : "+f"(c0), "+f"(c1), "+f"(c2), "+f"(c3)
        : "r"(a0), "r"(a1), "r"(a2), "r"(a3), "r"(b0), "r"(b1));
}

// ---------------------------------------------------------------------------
// rna(tf32) elementwise conversion
// ---------------------------------------------------------------------------
__global__ void convert_rna_kernel(const float* __restrict__ src,
                                   float* __restrict__ dst, int n4) {
    int i = blockIdx.x * blockDim.x + threadIdx.x;
    if (i < n4) {
        float4 v = ((const float4*)src)[i];
        v.x = rna_tf32(v.x); v.y = rna_tf32(v.y);
        v.z = rna_tf32(v.z); v.w = rna_tf32(v.w);
        ((float4*)dst)[i] = v;
    }
}

// ---------------------------------------------------------------------------
// transpose + rna: Wt[n][k] = rna(W[k][n]).  W: [K,N] row-major.
// ---------------------------------------------------------------------------
__global__ void transpose_rna_kernel(const float* __restrict__ W,
                                     float* __restrict__ Wt, int K, int N) {
    __shared__ float t[32][33];
    const int n0 = blockIdx.x * 32, k0 = blockIdx.y * 32;
    const int x = threadIdx.x, y = threadIdx.y;  // 32 x 8
    #pragma unroll
    for (int i = 0; i < 4; i++)
        t[y + i * 8][x] = W[(size_t)(k0 + y + i * 8) * N + n0 + x];
    __syncthreads();
    #pragma unroll
    for (int i = 0; i < 4; i++)
        Wt[(size_t)(n0 + y + i * 8) * K + k0 + x] = rna_tf32(t[x][y + i * 8]);
}

// ---------------------------------------------------------------------------
// tf32 mma.sync GEMM: C[M,N] = A[M,K] @ Bt[N,K]^T + bias[N]
// A, Bt row-major K-contiguous. 128x128 CTA tile, BK=16, 3-stage cp.async.
// 8 warps (2x4), warp tile 64x32 -> 4x4 m16n8k8 MMAs per k-step.
// ---------------------------------------------------------------------------
#define BK 16
#define SROW 20                      /* padded row stride (floats), 80B = 16B-aligned */
#define TILE_FLOATS (128 * SROW)     /* 2560 floats = 10240 B per matrix tile */
#define STAGE_FLOATS (2 * TILE_FLOATS)
#define NSTAGE 3
#define GEMM_SMEM (NSTAGE * STAGE_FLOATS * 4)   /* 61440 B */

__global__ __launch_bounds__(256)
void gemm_tf32_kernel(const float* __restrict__ A, const float* __restrict__ Bt,
                      const float* __restrict__ bias, float* __restrict__ C,
                      int M, int N, int K)
{
    extern __shared__ __align__(16) float sm[];

    const int tid  = threadIdx.x;
    const int wid  = tid >> 5;
    const int lane = tid & 31;
    const int wm   = (wid >> 2) * 64;   // warp row offset in CTA tile
    const int wn   = (wid & 3) * 32;    // warp col offset
    const int lr   = lane >> 2;         // 0..7
    const int lc   = lane & 3;          // 0..3
    const int n0   = blockIdx.x * 128;
    const int m0   = blockIdx.y * 128;
    const uint32_t smb = smem_u32(sm);

    float c[4][4][4];                   // [mt][nt][reg]
    #pragma unroll
    for (int i = 0; i < 4; i++)
        #pragma unroll
        for (int j = 0; j < 4; j++)
            #pragma unroll
            for (int r = 0; r < 4; r++) c[i][j][r] = 0.f;

    // stage loader: chunk index ch (k0 = ch*BK) -> stage s
    auto load_stage = [&](int ch, int s) {
        const float* Ab = A  + (size_t)m0 * K + ch * BK;
        const float* Bb = Bt + (size_t)n0 * K + ch * BK;
        const uint32_t sA = smb + (uint32_t)(s * STAGE_FLOATS) * 4u;
        const uint32_t sB = sA + TILE_FLOATS * 4u;
        #pragma unroll
        for (int i = 0; i < 2; i++) {
            const int chk = i * 256 + tid;      // 0..511
            const int row = chk >> 2, c4 = chk & 3;
            const uint32_t off = (uint32_t)(row * SROW + c4 * 4) * 4u;
            cp_async16(sA + off, Ab + (size_t)row * K + c4 * 4);
            cp_async16(sB + off, Bb + (size_t)row * K + c4 * 4);
        }
    };

    const int NCH = K / BK;

    load_stage(0, 0); cp_commit();
    load_stage(1, 1); cp_commit();

    for (int ch = 0; ch < NCH; ch++) {
        cp_wait<1>();
        __syncthreads();
        if (ch + 2 < NCH) load_stage(ch + 2, (ch + 2) % NSTAGE);
        cp_commit();

        const float* As = sm + (ch % NSTAGE) * STAGE_FLOATS;
        const float* Bs = As + TILE_FLOATS;

        #pragma unroll
        for (int ks = 0; ks < 2; ks++) {
            const int dk = ks * 8;
            uint32_t af[4][4], bf[4][2];
            #pragma unroll
            for (int mt = 0; mt < 4; mt++) {
                const float* ap = As + (wm + mt * 16 + lr) * SROW + dk + lc;
                af[mt][0] = __float_as_uint(ap[0]);
                af[mt][1] = __float_as_uint(ap[8 * SROW]);
                af[mt][2] = __float_as_uint(ap[4]);
                af[mt][3] = __float_as_uint(ap[8 * SROW + 4]);
            }
            #pragma unroll
            for (int nt = 0; nt < 4; nt++) {
                const float* bp = Bs + (wn + nt * 8 + lr) * SROW + dk + lc;
                bf[nt][0] = __float_as_uint(bp[0]);
                bf[nt][1] = __float_as_uint(bp[4]);
            }
            #pragma unroll
            for (int mt = 0; mt < 4; mt++)
                #pragma unroll
                for (int nt = 0; nt < 4; nt++)
                    mma_tf32(c[mt][nt][0], c[mt][nt][1], c[mt][nt][2], c[mt][nt][3],
                             af[mt][0], af[mt][1], af[mt][2], af[mt][3],
                             bf[nt][0], bf[nt][1]);
        }
        __syncthreads();
    }

    // epilogue: c0/c1 -> (row, 2*lc), (row, 2*lc+1); c2/c3 -> row+8
    #pragma unroll
    for (int nt = 0; nt < 4; nt++) {
        const int col = n0 + wn + nt * 8 + 2 * lc;
        const float b0 = bias[col], b1 = bias[col + 1];
        #pragma unroll
        for (int mt = 0; mt < 4; mt++) {
            const size_t r0 = (size_t)(m0 + wm + mt * 16 + lr);
            float2 v0 = make_float2(c[mt][nt][0] + b0, c[mt][nt][1] + b1);
            float2 v1 = make_float2(c[mt][nt][2] + b0, c[mt][nt][3] + b1);
            *(float2*)(&C[r0 * N + col])       = v0;
            *(float2*)(&C[(r0 + 8) * N + col]) = v1;
        }
    }
}

// ---------------------------------------------------------------------------
// Flash attention, fp32, causal + ALiBi (SIMT; proven correct in R1).
// Output stored rna(tf32)-rounded since it feeds the tf32 out-projection.
// ---------------------------------------------------------------------------
__global__ __launch_bounds__(256, 2)
void attn_kernel(const float* __restrict__ qkv, float* __restrict__ out)
{
    __shared__ __align__(16) float Qs[64 * 64];
    __shared__ __align__(16) float KPs[64 * 64];
    __shared__ __align__(16) float Vs[64 * 64];

    const int qt  = blockIdx.x;
    const int h   = blockIdx.y;
    const int b   = blockIdx.z;
    const int tid = threadIdx.x;
    const int tx  = tid & 15;
    const int ty  = tid >> 4;
    const int q0  = qt * 64;

    const float slope = exp2f(-0.5f * (float)(h + 1));

    const int lr = tid >> 2;
    const int lc = (tid & 3) << 4;

    const size_t rs = 3 * EMB;
    const float* base = qkv + (size_t)b * SEQ * rs + h * HDIM;

    {
        const float* g = base + (size_t)(q0 + lr) * rs + lc;
        #pragma unroll
        for (int j = 0; j < 16; j += 4) {
            float4 v = *(const float4*)(g + j);
            v.x *= 0.125f; v.y *= 0.125f; v.z *= 0.125f; v.w *= 0.125f;
            *(float4*)(&Qs[lr * 64 + lc + j]) = v;
        }
    }

    float m[4], l[4], o[4][4];
    #pragma unroll
    for (int i = 0; i < 4; i++) {
        m[i] = -1e30f; l[i] = 0.f;
        #pragma unroll
        for (int j = 0; j < 4; j++) o[i][j] = 0.f;
    }

    for (int kt = 0; kt <= qt; kt++) {
        __syncthreads();
        const int k0 = kt * 64;
        {
            const float* kg = base + EMB     + (size_t)(k0 + lr) * rs + lc;
            const float* vg = base + 2 * EMB + (size_t)(k0 + lr) * rs + lc;
            #pragma unroll
            for (int j = 0; j < 16; j += 4) {
                float4 kv = *(const float4*)(kg + j);
                KPs[(lc + j + 0) * 64 + lr] = kv.x;
                KPs[(lc + j + 1) * 64 + lr] = kv.y;
                KPs[(lc + j + 2) * 64 + lr] = kv.z;
                KPs[(lc + j + 3) * 64 + lr] = kv.w;
                float4 vv = *(const float4*)(vg + j);
                *(float4*)(&Vs[lr * 64 + lc + j]) = vv;
            }
        }
        __syncthreads();

        float s[4][4];
        #pragma unroll
        for (int i = 0; i < 4; i++)
            #pragma unroll
            for (int j = 0; j < 4; j++) s[i][j] = 0.f;

        #pragma unroll 8
        for (int d = 0; d < 64; d++) {
            float ra[4];
            #pragma unroll
            for (int i = 0; i < 4; i++) ra[i] = Qs[(ty * 4 + i) * 64 + d];
            float4 rb = *(const float4*)(&KPs[d * 64 + tx * 4]);
            #pragma unroll
            for (int i = 0; i < 4; i++) {
                s[i][0] += ra[i] * rb.x;
                s[i][1] += ra[i] * rb.y;
                s[i][2] += ra[i] * rb.z;
                s[i][3] += ra[i] * rb.w;
            }
        }

        #pragma unroll
        for (int i = 0; i < 4; i++) {
            const int qrow = q0 + ty * 4 + i;
            #pragma unroll
            for (int j = 0; j < 4; j++) {
                const int kcol = k0 + tx * 4 + j;
                s[i][j] += slope * (float)(kcol - qrow);
                if (kcol > qrow) s[i][j] = -1e30f;
            }
        }

        #pragma unroll
        for (int i = 0; i < 4; i++) {
            float tm = fmaxf(fmaxf(s[i][0], s[i][1]), fmaxf(s[i][2], s[i][3]));
            tm = fmaxf(tm, __shfl_xor_sync(0xffffffffu, tm, 1));
            tm = fmaxf(tm, __shfl_xor_sync(0xffffffffu, tm, 2));
            tm = fmaxf(tm, __shfl_xor_sync(0xffffffffu, tm, 4));
            tm = fmaxf(tm, __shfl_xor_sync(0xffffffffu, tm, 8));
            const float mn   = fmaxf(m[i], tm);
            const float corr = __expf(m[i] - mn);
            float ts = 0.f;
            #pragma unroll
            for (int j = 0; j < 4; j++) {
                s[i][j] = __expf(s[i][j] - mn);
                ts += s[i][j];
            }
            ts += __shfl_xor_sync(0xffffffffu, ts, 1);
            ts += __shfl_xor_sync(0xffffffffu, ts, 2);
            ts += __shfl_xor_sync(0xffffffffu, ts, 4);
            ts += __shfl_xor_sync(0xffffffffu, ts, 8);
            l[i] = l[i] * corr + ts;
            m[i] = mn;
            #pragma unroll
            for (int j = 0; j < 4; j++) o[i][j] *= corr;
        }

        __syncthreads();
        #pragma unroll
        for (int i = 0; i < 4; i++) {
            float4 pv = make_float4(s[i][0], s[i][1], s[i][2], s[i][3]);
            *(float4*)(&KPs[(ty * 4 + i) * 64 + tx * 4]) = pv;
        }
        __syncthreads();

        #pragma unroll 8
        for (int d = 0; d < 64; d++) {
            float pa[4];
            #pragma unroll
            for (int i = 0; i < 4; i++) pa[i] = KPs[(ty * 4 + i) * 64 + d];
            float4 vb = *(const float4*)(&Vs[d * 64 + tx * 4]);
            #pragma unroll
            for (int i = 0; i < 4; i++) {
                o[i][0] += pa[i] * vb.x;
                o[i][1] += pa[i] * vb.y;
                o[i][2] += pa[i] * vb.z;
                o[i][3] += pa[i] * vb.w;
            }
        }
    }

    float* og = out + ((size_t)b * SEQ + q0) * EMB + h * HDIM;
    #pragma unroll
    for (int i = 0; i < 4; i++) {
        const float inv = 1.f / l[i];
        float4 r = make_float4(rna_tf32(o[i][0] * inv), rna_tf32(o[i][1] * inv),
                               rna_tf32(o[i][2] * inv), rna_tf32(o[i][3] * inv));
        *(float4*)(&og[(size_t)(ty * 4 + i) * EMB + tx * 4]) = r;
    }
}

// ---------------------------------------------------------------------------
extern "C" void kernel_launch(void* const* d_in, const int* in_sizes, int n_in,
                              void* d_out, int out_size)
{
    const float* x    = (const float*)d_in[0];
    // d_in[1] = mask (bool tril) — causality handled analytically
    const float* Wqkv = (const float*)d_in[2];
    const float* bqkv = (const float*)d_in[3];
    const float* Wout = (const float*)d_in[4];
    const float* bout = (const float*)d_in[5];
    float* out = (float*)d_out;

    float *qkv_p, *att_p, *xc_p, *wqt_p, *wot_p;
    cudaGetSymbolAddress((void**)&qkv_p, g_qkv);
    cudaGetSymbolAddress((void**)&att_p, g_att);
    cudaGetSymbolAddress((void**)&xc_p,  g_xc);
    cudaGetSymbolAddress((void**)&wqt_p, g_wqt);
    cudaGetSymbolAddress((void**)&wot_p, g_wot);

    cudaFuncSetAttribute(gemm_tf32_kernel,
                         cudaFuncAttributeMaxDynamicSharedMemorySize, GEMM_SMEM);

    // 0) tf32-round operands
    {
        const int n4 = MROWS * EMB / 4;
        convert_rna_kernel<<<(n4 + 255) / 256, 256>>>(x, xc_p, n4);
    }
    transpose_rna_kernel<<<dim3(3 * EMB / 32, EMB / 32), dim3(32, 8)>>>(Wqkv, wqt_p, EMB, 3 * EMB);
    transpose_rna_kernel<<<dim3(EMB / 32, EMB / 32),     dim3(32, 8)>>>(Wout, wot_p, EMB, EMB);

    // 1) qkv = x @ W_qkv + b_qkv   (tf32 mma.sync)
    gemm_tf32_kernel<<<dim3(3 * EMB / 128, MROWS / 128), 256, GEMM_SMEM>>>(
        xc_p, wqt_p, bqkv, qkv_p, MROWS, 3 * EMB, EMB);

    // 2) attention (causal + ALiBi + softmax)
    attn_kernel<<<dim3(SEQ / 64, HEADS, BATCH), 256>>>(qkv_p, att_p);

    // 3) out = att @ W_out + b_out (tf32 mma.sync)
    gemm_tf32_kernel<<<dim3(EMB / 128, MROWS / 128), 256, GEMM_SMEM>>>(
        att_p, wot_p, bout, out, MROWS, EMB, EMB);
}

// round 4
// speedup vs baseline: 3.1331x; 1.9435x over previous
#include <cuda_runtime.h>
#include <cstdint>
#include <math.h>

#define BATCH 4
#define SEQ   2048
#define EMB   1024
#define HEADS 16
#define HDIM  64
#define MROWS (BATCH*SEQ)   /* 8192 */
#define L2E   1.4426950408889634f

// Scratch (device globals: allocation-free per harness rules)
__device__ float g_qkv[(size_t)MROWS * 3 * EMB];   // [8192, 3072] rna(tf32), Q pre-scaled
__device__ float g_att[(size_t)MROWS * EMB];       // [8192, 1024] rna(tf32)
__device__ float g_xc [(size_t)MROWS * EMB];       // x, rna(tf32)
__device__ float g_wqt[(size_t)3 * EMB * EMB];     // W_qkv^T, rna
__device__ float g_wot[(size_t)EMB * EMB];         // W_out^T, rna

// ---------------------------------------------------------------------------
// helpers (portable PTX only)
// ---------------------------------------------------------------------------
__device__ __forceinline__ uint32_t smem_u32(const void* p) {
    uint32_t a;
    asm("{ .reg .u64 t; cvta.to.shared.u64 t, %1; cvt.u32.u64 %0, t; }" : "=r"(a) : "l"(p));
    return a;
}
__device__ __forceinline__ float rna_tf32(float v) {
    uint32_t u;
    asm("cvt.rna.tf32.f32 %0, %1;" : "=r"(u) : "f"(v));
    return __uint_as_float(u);
}
__device__ __forceinline__ float fexp2(float x) {
    float y;
    asm("ex2.approx.f32 %0, %1;" : "=f"(y) : "f"(x));
    return y;
}
__device__ __forceinline__ void cp_async16(uint32_t dst, const void* src) {
    asm volatile("cp.async.cg.shared.global [%0], [%1], 16;" :: "r"(dst), "l"(src));
}
__device__ __forceinline__ void cp_commit() {
    asm volatile("cp.async.commit_group;" ::: "memory");
}
template <int N>
__device__ __forceinline__ void cp_wait() {
    asm volatile("cp.async.wait_group %0;" :: "n"(N) : "memory");
}
__device__ __forceinline__ void mma_tf32(float& c0, float& c1, float& c2, float& c3,
                                         uint32_t a0, uint32_t a1, uint32_t a2, uint32_t a3,
                                         uint32_t b0, uint32_t b1) {
    asm volatile(
        "mma.sync.aligned.m16n8k8.row.col.f32.tf32.tf32.f32 "
        "{%0,%1,%2,%3}, {%4,%5,%6,%7}, {%8,%9}, {%0,%1,%2,%3};"
        : "+f"(c0), "+f"(c1), "+f"(c2), "+f"(c3)
        : "r"(a0), "r"(a1), "r"(a2), "r"(a3), "r"(b0), "r"(b1));
}

// ---------------------------------------------------------------------------
__global__ void convert_rna_kernel(const float* __restrict__ src,
                                   float* __restrict__ dst, int n4) {
    int i = blockIdx.x * blockDim.x + threadIdx.x;
    if (i < n4) {
        float4 v = ((const float4*)src)[i];
        v.x = rna_tf32(v.x); v.y = rna_tf32(v.y);
        v.z = rna_tf32(v.z); v.w = rna_tf32(v.w);
        ((float4*)dst)[i] = v;
    }
}

__global__ void transpose_rna_kernel(const float* __restrict__ W,
                                     float* __restrict__ Wt, int K, int N) {
    __shared__ float t[32][33];
    const int n0 = blockIdx.x * 32, k0 = blockIdx.y * 32;
    const int x = threadIdx.x, y = threadIdx.y;  // 32 x 8
    #pragma unroll
    for (int i = 0; i < 4; i++)
        t[y + i * 8][x] = W[(size_t)(k0 + y + i * 8) * N + n0 + x];
    __syncthreads();
    #pragma unroll
    for (int i = 0; i < 4; i++)
        Wt[(size_t)(n0 + y + i * 8) * K + k0 + x] = rna_tf32(t[x][y + i * 8]);
}

// ---------------------------------------------------------------------------
// tf32 mma.sync GEMM (as R3) + mode: mode=1 -> rna output, Q cols (<1024) x0.125
// ---------------------------------------------------------------------------
#define BK 16
#define SROW 20
#define TILE_FLOATS (128 * SROW)
#define STAGE_FLOATS (2 * TILE_FLOATS)
#define NSTAGE 3
#define GEMM_SMEM (NSTAGE * STAGE_FLOATS * 4)

__global__ __launch_bounds__(256)
void gemm_tf32_kernel(const float* __restrict__ A, const float* __restrict__ Bt,
                      const float* __restrict__ bias, float* __restrict__ C,
                      int M, int N, int K, int mode)
{
    extern __shared__ __align__(16) float sm[];

    const int tid  = threadIdx.x;
    const int wid  = tid >> 5;
    const int lane = tid & 31;
    const int wm   = (wid >> 2) * 64;
    const int wn   = (wid & 3) * 32;
    const int lr   = lane >> 2;
    const int lc   = lane & 3;
    const int n0   = blockIdx.x * 128;
    const int m0   = blockIdx.y * 128;
    const uint32_t smb = smem_u32(sm);

    float c[4][4][4];
    #pragma unroll
    for (int i = 0; i < 4; i++)
        #pragma unroll
        for (int j = 0; j < 4; j++)
            #pragma unroll
            for (int r = 0; r < 4; r++) c[i][j][r] = 0.f;

    auto load_stage = [&](int ch, int s) {
        const float* Ab = A  + (size_t)m0 * K + ch * BK;
        const float* Bb = Bt + (size_t)n0 * K + ch * BK;
        const uint32_t sA = smb + (uint32_t)(s * STAGE_FLOATS) * 4u;
        const uint32_t sB = sA + TILE_FLOATS * 4u;
        #pragma unroll
        for (int i = 0; i < 2; i++) {
            const int chk = i * 256 + tid;
            const int row = chk >> 2, c4 = chk & 3;
            const uint32_t off = (uint32_t)(row * SROW + c4 * 4) * 4u;
            cp_async16(sA + off, Ab + (size_t)row * K + c4 * 4);
            cp_async16(sB + off, Bb + (size_t)row * K + c4 * 4);
        }
    };

    const int NCH = K / BK;

    load_stage(0, 0); cp_commit();
    load_stage(1, 1); cp_commit();

    for (int ch = 0; ch < NCH; ch++) {
        cp_wait<1>();
        __syncthreads();
        if (ch + 2 < NCH) load_stage(ch + 2, (ch + 2) % NSTAGE);
        cp_commit();

        const float* As = sm + (ch % NSTAGE) * STAGE_FLOATS;
        const float* Bs = As + TILE_FLOATS;

        #pragma unroll
        for (int ks = 0; ks < 2; ks++) {
            const int dk = ks * 8;
            uint32_t af[4][4], bf[4][2];
            #pragma unroll
            for (int mt = 0; mt < 4; mt++) {
                const float* ap = As + (wm + mt * 16 + lr) * SROW + dk + lc;
                af[mt][0] = __float_as_uint(ap[0]);
                af[mt][1] = __float_as_uint(ap[8 * SROW]);
                af[mt][2] = __float_as_uint(ap[4]);
                af[mt][3] = __float_as_uint(ap[8 * SROW + 4]);
            }
            #pragma unroll
            for (int nt = 0; nt < 4; nt++) {
                const float* bp = Bs + (wn + nt * 8 + lr) * SROW + dk + lc;
                bf[nt][0] = __float_as_uint(bp[0]);
                bf[nt][1] = __float_as_uint(bp[4]);
            }
            #pragma unroll
            for (int mt = 0; mt < 4; mt++)
                #pragma unroll
                for (int nt = 0; nt < 4; nt++)
                    mma_tf32(c[mt][nt][0], c[mt][nt][1], c[mt][nt][2], c[mt][nt][3],
                             af[mt][0], af[mt][1], af[mt][2], af[mt][3],
                             bf[nt][0], bf[nt][1]);
        }
        __syncthreads();
    }

    #pragma unroll
    for (int nt = 0; nt < 4; nt++) {
        const int col = n0 + wn + nt * 8 + 2 * lc;
        const float b0 = bias[col], b1 = bias[col + 1];
        const float sc = (mode && col < 1024) ? 0.125f : 1.0f;
        #pragma unroll
        for (int mt = 0; mt < 4; mt++) {
            const size_t r0 = (size_t)(m0 + wm + mt * 16 + lr);
            float v0 = (c[mt][nt][0] + b0) * sc;
            float v1 = (c[mt][nt][1] + b1) * sc;
            float v2 = (c[mt][nt][2] + b0) * sc;
            float v3 = (c[mt][nt][3] + b1) * sc;
            if (mode) {
                v0 = rna_tf32(v0); v1 = rna_tf32(v1);
                v2 = rna_tf32(v2); v3 = rna_tf32(v3);
            }
            *(float2*)(&C[r0 * N + col])       = make_float2(v0, v1);
            *(float2*)(&C[(r0 + 8) * N + col]) = make_float2(v2, v3);
        }
    }
}

// ---------------------------------------------------------------------------
// Flash attention with tf32 mma.sync. CTA = (qt 128 rows, h, b). 8 warps x 16 rows.
// qkv already rna(tf32)-rounded, Q pre-scaled by 1/8 (GEMM1 epilogue mode=1).
// ---------------------------------------------------------------------------
#define QS_OFF 0                 /* Q  [128][68]  */
#define PS_OFF 8704              /* P  [128][132] */
#define KS_OFF 25600             /* K  [128][68]  */
#define VR_OFF 34304             /* V  [128][68]  */
#define VT_OFF 43008             /* Vt [64][132]  */
#define ATT_SMEM ((43008 + 64 * 132) * 4)   /* 205824 B */

__global__ __launch_bounds__(256, 1)
void attn_mma_kernel(const float* __restrict__ qkv, float* __restrict__ out)
{
    extern __shared__ __align__(16) float sa[];

    const int tid  = threadIdx.x;
    const int wid  = tid >> 5;
    const int lane = tid & 31;
    const int lr   = lane >> 2;
    const int lc   = lane & 3;
    const int wm   = wid * 16;
    const int qt   = blockIdx.x;
    const int h    = blockIdx.y;
    const int b    = blockIdx.z;
    const int q0   = qt * 128;
    const float slope = fexp2(-0.5f * (float)(h + 1));
    const uint32_t smb = smem_u32(sa);

    const float* baseQ = qkv + (size_t)b * SEQ * 3072 + h * 64;
    const float* baseK = baseQ + 1024;
    const float* baseV = baseQ + 2048;

    auto load_tile = [&](const float* g, int row0, int soff) {
        #pragma unroll
        for (int i = 0; i < 8; i++) {
            const int chk = i * 256 + tid;          // 0..2047
            const int row = chk >> 4, c4 = chk & 15;
            cp_async16(smb + (uint32_t)(soff + row * 68 + c4 * 4) * 4u,
                       g + (size_t)(row0 + row) * 3072 + c4 * 4);
        }
    };

    load_tile(baseQ, q0, QS_OFF); cp_commit();
    load_tile(baseK, 0,  KS_OFF); cp_commit();
    load_tile(baseV, 0,  VR_OFF); cp_commit();

    float m0 = -1e30f, m1 = -1e30f, l0 = 0.f, l1 = 0.f;
    float o[8][4];
    #pragma unroll
    for (int i = 0; i < 8; i++)
        #pragma unroll
        for (int r = 0; r < 4; r++) o[i][r] = 0.f;

    const int qrow0 = q0 + wm + lr;
    const int qrow1 = qrow0 + 8;

    for (int kt = 0; kt <= qt; kt++) {
        cp_wait<1>();          // K(kt) (and Q) resident; V(kt) may still fly
        __syncthreads();

        // ---- S = Q @ K^T ----
        float c[16][4];
        #pragma unroll
        for (int nt = 0; nt < 16; nt++)
            #pragma unroll
            for (int r = 0; r < 4; r++) c[nt][r] = 0.f;

        #pragma unroll
        for (int dk = 0; dk < 8; dk++) {
            const float* ap = sa + QS_OFF + (wm + lr) * 68 + dk * 8 + lc;
            const uint32_t a0 = __float_as_uint(ap[0]);
            const uint32_t a1 = __float_as_uint(ap[8 * 68]);
            const uint32_t a2 = __float_as_uint(ap[4]);
            const uint32_t a3 = __float_as_uint(ap[8 * 68 + 4]);
            #pragma unroll
            for (int nt = 0; nt < 16; nt++) {
                const float* bp = sa + KS_OFF + (nt * 8 + lr) * 68 + dk * 8 + lc;
                mma_tf32(c[nt][0], c[nt][1], c[nt][2], c[nt][3],
                         a0, a1, a2, a3,
                         __float_as_uint(bp[0]), __float_as_uint(bp[4]));
            }
        }
        __syncthreads();       // done reading Ks
        if (kt < qt) load_tile(baseK, (kt + 1) * 128, KS_OFF);
        cp_commit();

        // ---- ALiBi + (diagonal-only) mask + online softmax ----
        const int kb = kt * 128 + 2 * lc;
        {
            float al0 = slope * (float)(kb - qrow0);
            float al1 = slope * (float)(kb - qrow1);
            const float st8 = 8.f * slope;
            float mx0 = -1e30f, mx1 = -1e30f;
            #pragma unroll
            for (int nt = 0; nt < 16; nt++) {
                float s0 = c[nt][0] + al0;
                float s1 = c[nt][1] + al0 + slope;
                float s2 = c[nt][2] + al1;
                float s3 = c[nt][3] + al1 + slope;
                if (kt == qt) {       // masking only possible on the diagonal tile
                    const int k0c = kb + nt * 8, k1c = k0c + 1;
                    if (k0c > qrow0) s0 = -1e30f;
                    if (k1c > qrow0) s1 = -1e30f;
                    if (k0c > qrow1) s2 = -1e30f;
                    if (k1c > qrow1) s3 = -1e30f;
                }
                c[nt][0] = s0; c[nt][1] = s1; c[nt][2] = s2; c[nt][3] = s3;
                mx0 = fmaxf(mx0, fmaxf(s0, s1));
                mx1 = fmaxf(mx1, fmaxf(s2, s3));
                al0 += st8; al1 += st8;
            }
            mx0 = fmaxf(mx0, __shfl_xor_sync(0xffffffffu, mx0, 1));
            mx0 = fmaxf(mx0, __shfl_xor_sync(0xffffffffu, mx0, 2));
            mx1 = fmaxf(mx1, __shfl_xor_sync(0xffffffffu, mx1, 1));
            mx1 = fmaxf(mx1, __shfl_xor_sync(0xffffffffu, mx1, 2));

            const float mn0 = fmaxf(m0, mx0), mn1 = fmaxf(m1, mx1);
            const float corr0 = fexp2((m0 - mn0) * L2E);
            const float corr1 = fexp2((m1 - mn1) * L2E);
            m0 = mn0; m1 = mn1;

            float ts0 = 0.f, ts1 = 0.f;
            float* p0 = sa + PS_OFF + (wm + lr) * 132 + 2 * lc;
            float* p1 = p0 + 8 * 132;
            #pragma unroll
            for (int nt = 0; nt < 16; nt++) {
                const float e0 = rna_tf32(fexp2((c[nt][0] - mn0) * L2E));
                const float e1 = rna_tf32(fexp2((c[nt][1] - mn0) * L2E));
                const float e2 = rna_tf32(fexp2((c[nt][2] - mn1) * L2E));
                const float e3 = rna_tf32(fexp2((c[nt][3] - mn1) * L2E));
                ts0 += e0 + e1;
                ts1 += e2 + e3;
                *(float2*)(p0 + nt * 8) = make_float2(e0, e1);
                *(float2*)(p1 + nt * 8) = make_float2(e2, e3);
            }
            ts0 += __shfl_xor_sync(0xffffffffu, ts0, 1);
            ts0 += __shfl_xor_sync(0xffffffffu, ts0, 2);
            ts1 += __shfl_xor_sync(0xffffffffu, ts1, 1);
            ts1 += __shfl_xor_sync(0xffffffffu, ts1, 2);
            l0 = l0 * corr0 + ts0;
            l1 = l1 * corr1 + ts1;
            #pragma unroll
            for (int i = 0; i < 8; i++) {
                o[i][0] *= corr0; o[i][1] *= corr0;
                o[i][2] *= corr1; o[i][3] *= corr1;
            }
        }

        cp_wait<1>();          // V(kt) resident; K(kt+1) may still fly
        __syncthreads();

        // ---- transpose V [128][64] -> Vt [64][128] ----
        {
            const int kvr = tid & 127;
            const int dc  = (tid >> 7) * 32;
            #pragma unroll
            for (int j = 0; j < 32; j += 4) {
                float4 v = *(const float4*)(sa + VR_OFF + kvr * 68 + dc + j);
                sa[VT_OFF + (dc + j + 0) * 132 + kvr] = v.x;
                sa[VT_OFF + (dc + j + 1) * 132 + kvr] = v.y;
                sa[VT_OFF + (dc + j + 2) * 132 + kvr] = v.z;
                sa[VT_OFF + (dc + j + 3) * 132 + kvr] = v.w;
            }
        }
        __syncthreads();

        // ---- O += P @ V ----
        #pragma unroll
        for (int dk = 0; dk < 16; dk++) {
            const float* pp = sa + PS_OFF + (wm + lr) * 132 + dk * 8 + lc;
            const uint32_t a0 = __float_as_uint(pp[0]);
            const uint32_t a1 = __float_as_uint(pp[8 * 132]);
            const uint32_t a2 = __float_as_uint(pp[4]);
            const uint32_t a3 = __float_as_uint(pp[8 * 132 + 4]);
            #pragma unroll
            for (int nt2 = 0; nt2 < 8; nt2++) {
                const float* bp = sa + VT_OFF + (nt2 * 8 + lr) * 132 + dk * 8 + lc;
                mma_tf32(o[nt2][0], o[nt2][1], o[nt2][2], o[nt2][3],
                         a0, a1, a2, a3,
                         __float_as_uint(bp[0]), __float_as_uint(bp[4]));
            }
        }
        __syncthreads();       // all warps done with Vt (and Vrm consumed)
        if (kt < qt) load_tile(baseV, (kt + 1) * 128, VR_OFF);
        cp_commit();
    }

    // ---- epilogue: normalize, rna (feeds tf32 out-projection) ----
    const float inv0 = 1.f / l0, inv1 = 1.f / l1;
    float* og = out + ((size_t)b * SEQ + qrow0) * EMB + h * HDIM + 2 * lc;
    #pragma unroll
    for (int nt2 = 0; nt2 < 8; nt2++) {
        *(float2*)(og + nt2 * 8) =
            make_float2(rna_tf32(o[nt2][0] * inv0), rna_tf32(o[nt2][1] * inv0));
        *(float2*)(og + 8 * EMB + nt2 * 8) =
            make_float2(rna_tf32(o[nt2][2] * inv1), rna_tf32(o[nt2][3] * inv1));
    }
}

// ---------------------------------------------------------------------------
extern "C" void kernel_launch(void* const* d_in, const int* in_sizes, int n_in,
                              void* d_out, int out_size)
{
    const float* x    = (const float*)d_in[0];
    // d_in[1] = mask (bool tril) — causality handled analytically
    const float* Wqkv = (const float*)d_in[2];
    const float* bqkv = (const float*)d_in[3];
    const float* Wout = (const float*)d_in[4];
    const float* bout = (const float*)d_in[5];
    float* out = (float*)d_out;

    float *qkv_p, *att_p, *xc_p, *wqt_p, *wot_p;
    cudaGetSymbolAddress((void**)&qkv_p, g_qkv);
    cudaGetSymbolAddress((void**)&att_p, g_att);
    cudaGetSymbolAddress((void**)&xc_p,  g_xc);
    cudaGetSymbolAddress((void**)&wqt_p, g_wqt);
    cudaGetSymbolAddress((void**)&wot_p, g_wot);

    cudaFuncSetAttribute(gemm_tf32_kernel,
                         cudaFuncAttributeMaxDynamicSharedMemorySize, GEMM_SMEM);
    cudaFuncSetAttribute(attn_mma_kernel,
                         cudaFuncAttributeMaxDynamicSharedMemorySize, ATT_SMEM);

    // 0) tf32-round operands
    {
        const int n4 = MROWS * EMB / 4;
        convert_rna_kernel<<<(n4 + 255) / 256, 256>>>(x, xc_p, n4);
    }
    transpose_rna_kernel<<<dim3(3 * EMB / 32, EMB / 32), dim3(32, 8)>>>(Wqkv, wqt_p, EMB, 3 * EMB);
    transpose_rna_kernel<<<dim3(EMB / 32, EMB / 32),     dim3(32, 8)>>>(Wout, wot_p, EMB, EMB);

    // 1) qkv = x @ W_qkv + b_qkv; epilogue rna + Q*0.125 (mode=1)
    gemm_tf32_kernel<<<dim3(3 * EMB / 128, MROWS / 128), 256, GEMM_SMEM>>>(
        xc_p, wqt_p, bqkv, qkv_p, MROWS, 3 * EMB, EMB, 1);

    // 2) attention (tf32 mma.sync, causal + ALiBi fused)
    attn_mma_kernel<<<dim3(SEQ / 128, HEADS, BATCH), 256, ATT_SMEM>>>(qkv_p, att_p);

    // 3) out = att @ W_out + b_out (mode=0: plain fp32 output)
    gemm_tf32_kernel<<<dim3(EMB / 128, MROWS / 128), 256, GEMM_SMEM>>>(
        att_p, wot_p, bout, out, MROWS, EMB, EMB, 0);
}